// round 12
// baseline (speedup 1.0000x reference)
#include <cuda_runtime.h>
#include <cuda_fp16.h>
#include <cstdint>
#include <math.h>

// ---------------------------------------------------------------------------
// BertAdapter fused: out = x + (gelu_new(LN(x) @ Wd + bd) @ Wu + bu)
// f16 datapath. 64-row CTAs, 256 threads, 3 CTAs/SM (24 warps/SM).
// GEMM1: f16 accumulator (32 regs). GEMM2: f32 acc, 16 n-chunks.
// Single-buffered smem stages; cross-CTA occupancy hides latency.
// mma.sync m16n8k16 (plain sm_103 target: no tcgen05).
// ---------------------------------------------------------------------------

#define TOKENS   32768
#define HIDDEN   1024
#define ADAPTER  256

__device__ __half g_wdT[HIDDEN * ADAPTER];   // wdT[n*1024 + k] = wd[k][n]
__device__ __half g_wuT[ADAPTER * HIDDEN];   // wuT[n*256  + k] = wu[k][n]

// ---------------- helpers ----------------
static __device__ __forceinline__ uint32_t smem_u32(const void* p) {
    uint32_t a;
    asm("{ .reg .u64 t; cvta.to.shared.u64 t, %1; cvt.u32.u64 %0, t; }"
        : "=r"(a) : "l"(p));
    return a;
}
static __device__ __forceinline__ uint32_t sw128(uint32_t o) {
    return o ^ ((o >> 3) & 0x70);
}

#define LDMATRIX_X4(r0, r1, r2, r3, addr)                                      \
    asm volatile("ldmatrix.sync.aligned.m8n8.x4.shared.b16 {%0,%1,%2,%3}, [%4];" \
                 : "=r"(r0), "=r"(r1), "=r"(r2), "=r"(r3) : "r"(addr))

// f16 x f16 -> f16 accumulate (2 acc regs)
#define MMA_F16(d, a, bb0, bb1)                                                \
    asm volatile(                                                              \
        "mma.sync.aligned.m16n8k16.row.col.f16.f16.f16.f16 "                   \
        "{%0,%1}, {%2,%3,%4,%5}, {%6,%7}, {%0,%1};"                            \
        : "+r"((d)[0]), "+r"((d)[1])                                           \
        : "r"((a)[0]), "r"((a)[1]), "r"((a)[2]), "r"((a)[3]),                  \
          "r"(bb0), "r"(bb1))

// f16 x f16 -> f32 accumulate (4 acc regs)
#define MMA_F32(d, a, bb0, bb1)                                                \
    asm volatile(                                                              \
        "mma.sync.aligned.m16n8k16.row.col.f32.f16.f16.f32 "                   \
        "{%0,%1,%2,%3}, {%4,%5,%6,%7}, {%8,%9}, {%0,%1,%2,%3};"                \
        : "+f"((d)[0]), "+f"((d)[1]), "+f"((d)[2]), "+f"((d)[3])               \
        : "r"((a)[0]), "r"((a)[1]), "r"((a)[2]), "r"((a)[3]),                  \
          "r"(bb0), "r"(bb1))

#define CP_ASYNC16(dst, src)                                                   \
    asm volatile("cp.async.cg.shared.global [%0], [%1], 16;"                   \
                 :: "r"(dst), "l"(src))
#define CP_COMMIT() asm volatile("cp.async.commit_group;" ::: "memory")
#define CP_WAIT0()  asm volatile("cp.async.wait_group 0;" ::: "memory")

static __device__ __forceinline__ float gelu_new_f(float x) {
    float x3 = x * x * x;
    float t = tanhf(0.7978845608028654f * (x + 0.044715f * x3));
    return 0.5f * x * (1.0f + t);
}

// smem map (relative to 1024-aligned base), 74752 B total -> 3 CTAs/SM:
//   0     : s_mu[64]; 256: s_rs[64]
//   1024  : P: 4 panels x (64 rows x 128B) = 32KB   [1024, 33792)
//   33792 : A buf (64 x 128B = 8KB)                 [33792, 41984)
//   41984 : B buf 32KB (G1: Wd 256x64k; G2: Wu chunk 64n x 256k as 4 panels)
//           [41984, 74752)
#define S_P  1024u
#define S_A  33792u
#define S_B  41984u
#define SMEM_BYTES (74752 + 1024)

// ---------------- prep: transpose + f16 convert weights ----------------
__global__ void __launch_bounds__(256) prep_w(const float* __restrict__ wd,
                                              const float* __restrict__ wu) {
    int i = blockIdx.x * 256 + threadIdx.x;            // 262144 total
    int n = i >> 10, k = i & 1023;
    g_wdT[i] = __float2half(wd[k * ADAPTER + n]);
    int n2 = i >> 8, k2 = i & 255;
    g_wuT[i] = __float2half(wu[k2 * HIDDEN + n2]);
}

// ---------------- the fused kernel ----------------
__global__ void __launch_bounds__(256, 3)
fused_kernel(const float* __restrict__ x, const float* __restrict__ lnw,
             const float* __restrict__ lnb, const float* __restrict__ bdown,
             const float* __restrict__ bup, float* __restrict__ out) {
    extern __shared__ char smem_raw[];
    const int tid = threadIdx.x, wid = tid >> 5, lid = tid & 31;
    const int m0 = blockIdx.x * 64;

    uint32_t sb0 = smem_u32(smem_raw);
    uint32_t pad = (1024u - (sb0 & 1023u)) & 1023u;
    char* smem = smem_raw + pad;
    uint32_t sb = sb0 + pad;
    float* s_mu = (float*)smem;
    float* s_rs = (float*)(smem + 256);

    const float4* x4 = (const float4*)x;
    const float4* w4 = (const float4*)lnw;
    const float4* b4 = (const float4*)lnb;
    const uint4* wdT4 = (const uint4*)g_wdT;
    const uint4* wuT4 = (const uint4*)g_wuT;

    // ===== phase 0: LN stats, one row per warp x 8 =====
#pragma unroll 1
    for (int r8 = 0; r8 < 8; r8++) {
        int row = wid * 8 + r8;
        const float4* p = x4 + (size_t)(m0 + row) * 256;
        float s = 0.f, ss = 0.f;
#pragma unroll
        for (int i = 0; i < 8; i++) {
            float4 v = p[lid + i * 32];
            s  += v.x + v.y + v.z + v.w;
            ss += v.x * v.x + v.y * v.y + v.z * v.z + v.w * v.w;
        }
#pragma unroll
        for (int o = 16; o; o >>= 1) {
            s  += __shfl_xor_sync(0xFFFFFFFFu, s, o);
            ss += __shfl_xor_sync(0xFFFFFFFFu, ss, o);
        }
        if (lid == 0) {
            float mu = s * (1.0f / 1024.0f);
            float var = ss * (1.0f / 1024.0f) - mu * mu;
            s_mu[row] = mu;
            s_rs[row] = rsqrtf(var + 1e-5f);
        }
    }
    __syncthreads();

    // ===== phase 1: GEMM1 (64x256, K=1024, BK=64), f16 acc ==================
    // warp grid 2m x 4n: warp tile 32m x 64n.
    const int wm1 = (wid & 1) * 32, wn1 = (wid >> 1) * 64;
    const int f4 = tid & 15;       // float4 col within 64-wide k-chunk
    const int mb = tid >> 4;       // 0..15, rows mb + i*16

    uint32_t acc1[2][8][2];        // f16 acc: 32 regs
#pragma unroll
    for (int mt = 0; mt < 2; mt++)
#pragma unroll
        for (int nt = 0; nt < 8; nt++) {
            acc1[mt][nt][0] = 0u; acc1[mt][nt][1] = 0u;
        }

#pragma unroll 1
    for (int kt = 0; kt < 16; kt++) {
        // B slice (Wd): 256 rows x 64k = 32KB, cp.async
#pragma unroll
        for (int i = 0; i < 8; i++) {
            int idx = tid + i * 256;
            int n = idx >> 3, u = idx & 7;
            uint32_t dst = sb + S_B + sw128((uint32_t)n * 128u + (uint32_t)u * 16u);
            CP_ASYNC16(dst, wdT4 + (size_t)n * 128 + kt * 8 + u);
        }
        CP_COMMIT();
        // A stage: LDG x -> LN -> f16 -> smem (overlaps the cp.async above)
        {
            int k4 = kt * 16 + f4;
            float4 wv = w4[k4], bv = b4[k4];
#pragma unroll
            for (int i = 0; i < 4; i++) {
                int m = mb + i * 16;
                float4 v = x4[(size_t)(m0 + m) * 256 + k4];
                float mu = s_mu[m], rs = s_rs[m];
                __half2 p0 = __floats2half2_rn((v.x - mu) * rs * wv.x + bv.x,
                                               (v.y - mu) * rs * wv.y + bv.y);
                __half2 p1 = __floats2half2_rn((v.z - mu) * rs * wv.z + bv.z,
                                               (v.w - mu) * rs * wv.w + bv.w);
                uint2 val;
                val.x = *(uint32_t*)&p0;
                val.y = *(uint32_t*)&p1;
                *(uint2*)(smem + S_A + sw128((uint32_t)m * 128u + (uint32_t)f4 * 8u)) = val;
            }
        }
        CP_WAIT0();
        __syncthreads();           // A+B stage visible

        // compute: 4 k16 steps
#pragma unroll
        for (int kk = 0; kk < 4; kk++) {
            uint32_t a[2][4];
#pragma unroll
            for (int mt = 0; mt < 2; mt++) {
                uint32_t off = (uint32_t)(wm1 + mt * 16 + (lid & 15)) * 128u +
                               (uint32_t)(kk * 32 + ((lid >> 4) << 4));
                LDMATRIX_X4(a[mt][0], a[mt][1], a[mt][2], a[mt][3],
                            sb + S_A + sw128(off));
            }
            uint32_t b[4][4];
#pragma unroll
            for (int g = 0; g < 4; g++) {
                uint32_t row = (uint32_t)(wn1 + g * 16 + (lid & 7) + ((lid >> 4) << 3));
                uint32_t off = row * 128u +
                               (uint32_t)(kk * 32 + (((lid >> 3) & 1) << 4));
                LDMATRIX_X4(b[g][0], b[g][1], b[g][2], b[g][3],
                            sb + S_B + sw128(off));
            }
#pragma unroll
            for (int mt = 0; mt < 2; mt++)
#pragma unroll
                for (int nt = 0; nt < 8; nt++) {
                    int g = nt >> 1;
                    if ((nt & 1) == 0) MMA_F16(acc1[mt][nt], a[mt], b[g][0], b[g][1]);
                    else               MMA_F16(acc1[mt][nt], a[mt], b[g][2], b[g][3]);
                }
        }
        __syncthreads();           // compute done; buffers reusable
    }

    // GELU epilogue -> P panels (4 x 64rows x 64cols f16) in smem
#pragma unroll
    for (int mt = 0; mt < 2; mt++)
#pragma unroll
        for (int nt = 0; nt < 8; nt++) {
            int col = wn1 + nt * 8 + (lid & 3) * 2;
            int row = wm1 + mt * 16 + (lid >> 2);
            float b0 = bdown[col], b1 = bdown[col + 1];
            float2 v0 = __half22float2(*(__half2*)&acc1[mt][nt][0]);
            float2 v1 = __half22float2(*(__half2*)&acc1[mt][nt][1]);
            __half2 p0 = __floats2half2_rn(gelu_new_f(v0.x + b0),
                                           gelu_new_f(v0.y + b1));
            __half2 p1 = __floats2half2_rn(gelu_new_f(v1.x + b0),
                                           gelu_new_f(v1.y + b1));
            uint32_t pan = (uint32_t)(col >> 6) * 8192u;
            uint32_t cin = (uint32_t)(col & 63) * 2u;
            *(uint32_t*)(smem + S_P + pan +
                         sw128((uint32_t)row * 128u + cin)) = *(uint32_t*)&p0;
            *(uint32_t*)(smem + S_P + pan +
                         sw128((uint32_t)(row + 8) * 128u + cin)) = *(uint32_t*)&p1;
        }
    __syncthreads();   // P visible

    // ===== phase 2: GEMM2 (64x1024, K=256), 16 n-chunks of 64, f32 acc =====
    // warp grid 2m x 4n: warp tile 32m x 16n.
    const int wm2 = (wid & 1) * 32, wn2 = (wid >> 1) * 16;
    const float2* x2  = (const float2*)x;
    const float2* bu2 = (const float2*)bup;
    float2* o2 = (float2*)out;

#pragma unroll 1
    for (int nc = 0; nc < 16; nc++) {
        // Wu chunk: 64 n-rows x 256k = 32KB as 4 panels (64 x 128B)
#pragma unroll
        for (int i = 0; i < 8; i++) {
            int idx = tid + i * 256;                // 0..2047
            int r = idx >> 5, u = idx & 31;         // 64 rows x 32 x 16B
            int q = u >> 3, u8 = u & 7;
            uint32_t dst = sb + S_B + (uint32_t)q * 8192u +
                           sw128((uint32_t)r * 128u + (uint32_t)u8 * 16u);
            CP_ASYNC16(dst, wuT4 + (size_t)(nc * 64 + r) * 32 + u);
        }
        CP_COMMIT();
        CP_WAIT0();
        __syncthreads();           // chunk visible; prev epilogue done

        float acc2[2][2][4];
#pragma unroll
        for (int mt = 0; mt < 2; mt++)
#pragma unroll
            for (int nt = 0; nt < 2; nt++)
#pragma unroll
                for (int j = 0; j < 4; j++) acc2[mt][nt][j] = 0.f;

#pragma unroll
        for (int p = 0; p < 4; p++) {
#pragma unroll
            for (int kk = 0; kk < 4; kk++) {
                uint32_t a[2][4];
#pragma unroll
                for (int mt = 0; mt < 2; mt++) {
                    uint32_t off = (uint32_t)(wm2 + mt * 16 + (lid & 15)) * 128u +
                                   (uint32_t)(kk * 32 + ((lid >> 4) << 4));
                    LDMATRIX_X4(a[mt][0], a[mt][1], a[mt][2], a[mt][3],
                                sb + S_P + (uint32_t)p * 8192u + sw128(off));
                }
                uint32_t b0, b1, b2, b3;
                {
                    uint32_t row = (uint32_t)(wn2 + (lid & 7) + ((lid >> 4) << 3));
                    uint32_t off = row * 128u +
                                   (uint32_t)(kk * 32 + (((lid >> 3) & 1) << 4));
                    LDMATRIX_X4(b0, b1, b2, b3,
                                sb + S_B + (uint32_t)p * 8192u + sw128(off));
                }
#pragma unroll
                for (int mt = 0; mt < 2; mt++) {
                    MMA_F32(acc2[mt][0], a[mt], b0, b1);
                    MMA_F32(acc2[mt][1], a[mt], b2, b3);
                }
            }
        }

        // epilogue: + bias + residual -> out
#pragma unroll
        for (int mt = 0; mt < 2; mt++)
#pragma unroll
            for (int nt = 0; nt < 2; nt++) {
                int col = nc * 64 + wn2 + nt * 8 + (lid & 3) * 2;
                int row = m0 + wm2 + mt * 16 + (lid >> 2);
                float2 bv = bu2[col >> 1];
                float* c = acc2[mt][nt];
                float2 r0 = x2[(size_t)row * 512 + (col >> 1)];
                float2 r1 = x2[(size_t)(row + 8) * 512 + (col >> 1)];
                float2 o0, o1;
                o0.x = c[0] + bv.x + r0.x;  o0.y = c[1] + bv.y + r0.y;
                o1.x = c[2] + bv.x + r1.x;  o1.y = c[3] + bv.y + r1.y;
                o2[(size_t)row * 512 + (col >> 1)]       = o0;
                o2[(size_t)(row + 8) * 512 + (col >> 1)] = o1;
            }
        __syncthreads();           // reads of chunk done before next load
    }
}

// ---------------- host launcher ----------------
extern "C" void kernel_launch(void* const* d_in, const int* in_sizes, int n_in,
                              void* d_out, int out_size) {
    const float* x   = (const float*)d_in[0];
    const float* lnw = (const float*)d_in[1];
    const float* lnb = (const float*)d_in[2];
    const float* wd  = (const float*)d_in[3];
    const float* bd  = (const float*)d_in[4];
    const float* wu  = (const float*)d_in[5];
    const float* bu  = (const float*)d_in[6];
    float* out = (float*)d_out;

    cudaFuncSetAttribute(fused_kernel, cudaFuncAttributeMaxDynamicSharedMemorySize,
                         SMEM_BYTES);

    prep_w<<<1024, 256>>>(wd, wu);
    fused_kernel<<<512, 256, SMEM_BYTES>>>(x, lnw, lnb, bd, bu, out);
    (void)in_sizes; (void)n_in; (void)out_size;
}

// round 13
// speedup vs baseline: 1.1734x; 1.1734x over previous
#include <cuda_runtime.h>
#include <cuda_bf16.h>
#include <cstdint>
#include <math.h>

// ---------------------------------------------------------------------------
// BertAdapter, 3-kernel split, every GEMM at 2 CTAs/SM:
//   prep_t : transpose+bf16 weights (smem tiles, coalesced)
//   g1     : stats + LN(x)@Wd + gelu -> inter   (128x128 tiles, 256thr, 2/SM)
//   g2     : inter@Wu + bias + residual -> out  (128x128 tiles, 256thr, 2/SM)
// mma.sync m16n8k16 bf16 (plain sm_103 target: no tcgen05).
// ---------------------------------------------------------------------------

#define TOKENS   32768
#define HIDDEN   1024
#define ADAPTER  256

__device__ __nv_bfloat16 g_wdT[HIDDEN * ADAPTER];   // wdT[n*1024 + k] = wd[k][n]
__device__ __nv_bfloat16 g_wuT[ADAPTER * HIDDEN];   // wuT[n*256  + k] = wu[k][n]
__device__ __nv_bfloat16 g_inter[TOKENS * ADAPTER]; // 16MB, L2-resident

// ---------------- helpers ----------------
static __device__ __forceinline__ uint32_t smem_u32(const void* p) {
    uint32_t a;
    asm("{ .reg .u64 t; cvta.to.shared.u64 t, %1; cvt.u32.u64 %0, t; }"
        : "=r"(a) : "l"(p));
    return a;
}
static __device__ __forceinline__ uint32_t sw128(uint32_t o) {
    return o ^ ((o >> 3) & 0x70);
}

#define LDMATRIX_X4(r0, r1, r2, r3, addr)                                      \
    asm volatile("ldmatrix.sync.aligned.m8n8.x4.shared.b16 {%0,%1,%2,%3}, [%4];" \
                 : "=r"(r0), "=r"(r1), "=r"(r2), "=r"(r3) : "r"(addr))

#define MMA_BF16(d, a, bb0, bb1)                                               \
    asm volatile(                                                              \
        "mma.sync.aligned.m16n8k16.row.col.f32.bf16.bf16.f32 "                 \
        "{%0,%1,%2,%3}, {%4,%5,%6,%7}, {%8,%9}, {%0,%1,%2,%3};"                \
        : "+f"((d)[0]), "+f"((d)[1]), "+f"((d)[2]), "+f"((d)[3])               \
        : "r"((a)[0]), "r"((a)[1]), "r"((a)[2]), "r"((a)[3]),                  \
          "r"(bb0), "r"(bb1))

#define CP_ASYNC16(dst, src)                                                   \
    asm volatile("cp.async.cg.shared.global [%0], [%1], 16;"                   \
                 :: "r"(dst), "l"(src))
#define CP_COMMIT() asm volatile("cp.async.commit_group;" ::: "memory")
#define CP_WAIT0()  asm volatile("cp.async.wait_group 0;" ::: "memory")

static __device__ __forceinline__ float gelu_new_f(float x) {
    float x3 = x * x * x;
    float t = tanhf(0.7978845608028654f * (x + 0.044715f * x3));
    return 0.5f * x * (1.0f + t);
}

struct Frag64 { float a[2][8][4]; };   // warp tile 32m x 64n

// A panel: 128 rows x 64k (rows 128B, SW128). B panel: 128 rows x 64k.
static __device__ __forceinline__ void tile_compute64(uint32_t ab, uint32_t bb,
                                                      int lid, int wm, int wn,
                                                      Frag64& f) {
#pragma unroll
    for (int kk = 0; kk < 4; kk++) {
        uint32_t a[2][4];
#pragma unroll
        for (int mt = 0; mt < 2; mt++) {
            uint32_t off = (uint32_t)(wm + mt * 16 + (lid & 15)) * 128u +
                           (uint32_t)(kk * 32 + ((lid >> 4) << 4));
            LDMATRIX_X4(a[mt][0], a[mt][1], a[mt][2], a[mt][3], ab + sw128(off));
        }
        uint32_t b[4][4];
#pragma unroll
        for (int g = 0; g < 4; g++) {
            uint32_t row = (uint32_t)(wn + g * 16 + (lid & 7) + ((lid >> 4) << 3));
            uint32_t off = row * 128u +
                           (uint32_t)(kk * 32 + (((lid >> 3) & 1) << 4));
            LDMATRIX_X4(b[g][0], b[g][1], b[g][2], b[g][3], bb + sw128(off));
        }
#pragma unroll
        for (int mt = 0; mt < 2; mt++)
#pragma unroll
            for (int nt = 0; nt < 8; nt++) {
                int g = nt >> 1;
                if ((nt & 1) == 0) MMA_BF16(f.a[mt][nt], a[mt], b[g][0], b[g][1]);
                else               MMA_BF16(f.a[mt][nt], a[mt], b[g][2], b[g][3]);
            }
    }
}

// ---------------- prep: smem-tile transpose + bf16 convert ----------------
__global__ void __launch_bounds__(256) prep_t(const float* __restrict__ wd,
                                              const float* __restrict__ wu) {
    __shared__ float t[32][33];
    int b = blockIdx.x;
    int r = threadIdx.x >> 5, c = threadIdx.x & 31;
    if (b < 256) {          // wd [1024k][256n] -> wdT [256n][1024k]
        int k0 = (b >> 3) * 32, n0 = (b & 7) * 32;
#pragma unroll
        for (int i = 0; i < 4; i++)
            t[r + i * 8][c] = wd[(size_t)(k0 + r + i * 8) * 256 + n0 + c];
        __syncthreads();
#pragma unroll
        for (int i = 0; i < 4; i++)
            g_wdT[(size_t)(n0 + r + i * 8) * 1024 + k0 + c] =
                __float2bfloat16(t[c][r + i * 8]);
    } else {                // wu [256k][1024n] -> wuT [1024n][256k]
        b -= 256;
        int k0 = (b & 7) * 32, n0 = (b >> 3) * 32;
#pragma unroll
        for (int i = 0; i < 4; i++)
            t[r + i * 8][c] = wu[(size_t)(k0 + r + i * 8) * 1024 + n0 + c];
        __syncthreads();
#pragma unroll
        for (int i = 0; i < 4; i++)
            g_wuT[(size_t)(n0 + r + i * 8) * 256 + k0 + c] =
                __float2bfloat16(t[c][r + i * 8]);
    }
}

// smem (1024-aligned): mu[128]@0, rs@512, A0@1024, A1@17408, B0@33792, B1@50176
#define G1_A0 1024u
#define G1_A1 17408u
#define G1_B0 33792u
#define G1_B1 50176u
#define G1_SMEM (66560 + 1024)

// ---------------- g1: stats + LN(x)@Wd + gelu -> inter --------------------
__global__ void __launch_bounds__(256, 2)
g1_kernel(const float* __restrict__ x, const float* __restrict__ lnw,
          const float* __restrict__ lnb, const float* __restrict__ bdown) {
    extern __shared__ char smem_raw[];
    const int tid = threadIdx.x, wid = tid >> 5, lid = tid & 31;
    const int m0 = (blockIdx.x >> 1) * 128;
    const int n0 = (blockIdx.x & 1) * 128;

    uint32_t sb0 = smem_u32(smem_raw);
    uint32_t pad = (1024u - (sb0 & 1023u)) & 1023u;
    char* smem = smem_raw + pad;
    uint32_t sb = sb0 + pad;
    float* s_mu = (float*)smem;
    float* s_rs = (float*)(smem + 512);

    const float4* x4 = (const float4*)x;
    const float4* w4 = (const float4*)lnw;
    const float4* b4 = (const float4*)lnb;
    const uint4* wdT4 = (const uint4*)g_wdT;

    // stats: 8 warps x 16 rows
#pragma unroll 1
    for (int r16 = 0; r16 < 16; r16++) {
        int row = wid * 16 + r16;
        const float4* p = x4 + (size_t)(m0 + row) * 256;
        float s = 0.f, ss = 0.f;
#pragma unroll
        for (int i = 0; i < 8; i++) {
            float4 v = p[lid + i * 32];
            s  += v.x + v.y + v.z + v.w;
            ss += v.x * v.x + v.y * v.y + v.z * v.z + v.w * v.w;
        }
#pragma unroll
        for (int o = 16; o; o >>= 1) {
            s  += __shfl_xor_sync(0xFFFFFFFFu, s, o);
            ss += __shfl_xor_sync(0xFFFFFFFFu, ss, o);
        }
        if (lid == 0) {
            float mu = s * (1.0f / 1024.0f);
            float var = ss * (1.0f / 1024.0f) - mu * mu;
            s_mu[row] = mu;
            s_rs[row] = rsqrtf(var + 1e-5f);
        }
    }
    __syncthreads();

    const int f4 = tid & 15;       // float4 col within 64-wide k-chunk
    const int mb = tid >> 4;       // 0..15, rows mb + i*16
    const int wm = (wid & 3) * 32, wn = (wid >> 2) * 64;

    auto stageA = [&](int kt, uint32_t aoff) {
        int k4 = kt * 16 + f4;
        float4 wv = w4[k4], bv = b4[k4];
#pragma unroll
        for (int i = 0; i < 8; i++) {
            int m = mb + i * 16;
            float4 v = x4[(size_t)(m0 + m) * 256 + k4];
            float mu = s_mu[m], rs = s_rs[m];
            __nv_bfloat162 p0 = __floats2bfloat162_rn(
                (v.x - mu) * rs * wv.x + bv.x, (v.y - mu) * rs * wv.y + bv.y);
            __nv_bfloat162 p1 = __floats2bfloat162_rn(
                (v.z - mu) * rs * wv.z + bv.z, (v.w - mu) * rs * wv.w + bv.w);
            uint2 val;
            val.x = *(uint32_t*)&p0;
            val.y = *(uint32_t*)&p1;
            *(uint2*)(smem + aoff + sw128((uint32_t)m * 128u + (uint32_t)f4 * 8u)) = val;
        }
    };
    auto loadB = [&](int kt, uint32_t bbuf) {   // Wd: 128 n-rows x 64 k = 16KB
#pragma unroll
        for (int i = 0; i < 4; i++) {
            int idx = tid + i * 256;
            int n = idx >> 3, u = idx & 7;
            uint32_t dst = bbuf + sw128((uint32_t)n * 128u + (uint32_t)u * 16u);
            CP_ASYNC16(dst, wdT4 + (size_t)(n0 + n) * 128 + kt * 8 + u);
        }
        CP_COMMIT();
    };

    Frag64 f1;
#pragma unroll
    for (int mt = 0; mt < 2; mt++)
#pragma unroll
        for (int nt = 0; nt < 8; nt++)
#pragma unroll
            for (int j = 0; j < 4; j++) f1.a[mt][nt][j] = 0.f;

    loadB(0, sb + G1_B0);
    stageA(0, G1_A0);
    CP_WAIT0();
    __syncthreads();

#pragma unroll 1
    for (int kt = 0; kt < 16; kt++) {
        int buf = kt & 1;
        if (kt + 1 < 16) loadB(kt + 1, sb + (buf ? G1_B0 : G1_B1));
        tile_compute64(sb + (buf ? G1_A1 : G1_A0),
                       sb + (buf ? G1_B1 : G1_B0), lid, wm, wn, f1);
        if (kt + 1 < 16) stageA(kt + 1, buf ? G1_A0 : G1_A1);
        CP_WAIT0();
        __syncthreads();
    }

    // gelu + bias -> inter (bf16)
    uint32_t* dst = (uint32_t*)g_inter;
#pragma unroll
    for (int mt = 0; mt < 2; mt++)
#pragma unroll
        for (int nt = 0; nt < 8; nt++) {
            int col = n0 + wn + nt * 8 + (lid & 3) * 2;
            int row = m0 + wm + mt * 16 + (lid >> 2);
            float b0 = bdown[col], b1 = bdown[col + 1];
            float* c = f1.a[mt][nt];
            __nv_bfloat162 p0 = __floats2bfloat162_rn(gelu_new_f(c[0] + b0),
                                                      gelu_new_f(c[1] + b1));
            __nv_bfloat162 p1 = __floats2bfloat162_rn(gelu_new_f(c[2] + b0),
                                                      gelu_new_f(c[3] + b1));
            dst[(size_t)row * 128 + (col >> 1)]       = *(uint32_t*)&p0;
            dst[(size_t)(row + 8) * 128 + (col >> 1)] = *(uint32_t*)&p1;
        }
}

// smem (1024-aligned): A0@0, A1@16384, B0@32768, B1@49152
#define G2_A0 0u
#define G2_A1 16384u
#define G2_B0 32768u
#define G2_B1 49152u
#define G2_SMEM (65536 + 1024)

// ---------------- g2: inter@Wu + bias + residual -> out -------------------
__global__ void __launch_bounds__(256, 2)
g2_kernel(const float* __restrict__ x, const float* __restrict__ bup,
          float* __restrict__ out) {
    extern __shared__ char smem_raw[];
    const int tid = threadIdx.x, wid = tid >> 5, lid = tid & 31;
    const int m0 = blockIdx.x * 128;
    const int n0 = blockIdx.y * 128;

    uint32_t sb0 = smem_u32(smem_raw);
    uint32_t pad = (1024u - (sb0 & 1023u)) & 1023u;
    uint32_t sb = sb0 + pad;

    const uint4* a4  = (const uint4*)g_inter;   // 32 uint4 per 256-bf16 row
    const uint4* wt4 = (const uint4*)g_wuT;     // 32 uint4 per 256-bf16 row

    auto loadAB = [&](int kt, uint32_t abuf, uint32_t bbuf) {   // 16KB each
#pragma unroll
        for (int i = 0; i < 4; i++) {
            int idx = tid + i * 256;
            int r = idx >> 3, u = idx & 7;
            uint32_t so = sw128((uint32_t)r * 128u + (uint32_t)u * 16u);
            CP_ASYNC16(abuf + so, a4  + (size_t)(m0 + r) * 32 + kt * 8 + u);
            CP_ASYNC16(bbuf + so, wt4 + (size_t)(n0 + r) * 32 + kt * 8 + u);
        }
        CP_COMMIT();
    };

    Frag64 f2;
#pragma unroll
    for (int mt = 0; mt < 2; mt++)
#pragma unroll
        for (int nt = 0; nt < 8; nt++)
#pragma unroll
            for (int j = 0; j < 4; j++) f2.a[mt][nt][j] = 0.f;

    const int wm = (wid & 3) * 32, wn = (wid >> 2) * 64;

    loadAB(0, sb + G2_A0, sb + G2_B0);
    CP_WAIT0();
    __syncthreads();

#pragma unroll 1
    for (int kt = 0; kt < 4; kt++) {
        int buf = kt & 1;
        if (kt + 1 < 4)
            loadAB(kt + 1, sb + (buf ? G2_A0 : G2_A1), sb + (buf ? G2_B0 : G2_B1));
        tile_compute64(sb + (buf ? G2_A1 : G2_A0),
                       sb + (buf ? G2_B1 : G2_B0), lid, wm, wn, f2);
        CP_WAIT0();
        __syncthreads();
    }

    // + bias + residual -> out
    const float2* x2  = (const float2*)x;
    const float2* bu2 = (const float2*)bup;
    float2* o2 = (float2*)out;
#pragma unroll
    for (int mt = 0; mt < 2; mt++)
#pragma unroll
        for (int nt = 0; nt < 8; nt++) {
            int col = n0 + wn + nt * 8 + (lid & 3) * 2;
            int row = m0 + wm + mt * 16 + (lid >> 2);
            float2 bv = bu2[col >> 1];
            float* c = f2.a[mt][nt];
            float2 r0 = x2[(size_t)row * 512 + (col >> 1)];
            float2 r1 = x2[(size_t)(row + 8) * 512 + (col >> 1)];
            float2 o0, o1;
            o0.x = c[0] + bv.x + r0.x;  o0.y = c[1] + bv.y + r0.y;
            o1.x = c[2] + bv.x + r1.x;  o1.y = c[3] + bv.y + r1.y;
            o2[(size_t)row * 512 + (col >> 1)]       = o0;
            o2[(size_t)(row + 8) * 512 + (col >> 1)] = o1;
        }
}

// ---------------- host launcher ----------------
extern "C" void kernel_launch(void* const* d_in, const int* in_sizes, int n_in,
                              void* d_out, int out_size) {
    const float* x   = (const float*)d_in[0];
    const float* lnw = (const float*)d_in[1];
    const float* lnb = (const float*)d_in[2];
    const float* wd  = (const float*)d_in[3];
    const float* bd  = (const float*)d_in[4];
    const float* wu  = (const float*)d_in[5];
    const float* bu  = (const float*)d_in[6];
    float* out = (float*)d_out;

    cudaFuncSetAttribute(g1_kernel, cudaFuncAttributeMaxDynamicSharedMemorySize,
                         G1_SMEM);
    cudaFuncSetAttribute(g2_kernel, cudaFuncAttributeMaxDynamicSharedMemorySize,
                         G2_SMEM);

    prep_t<<<512, 256>>>(wd, wu);
    g1_kernel<<<512, 256, G1_SMEM>>>(x, lnw, lnb, bd);
    g2_kernel<<<dim3(256, 8), 256, G2_SMEM>>>(x, bu, out);
    (void)in_sizes; (void)n_in; (void)out_size;
}

// round 14
// speedup vs baseline: 1.3131x; 1.1191x over previous
#include <cuda_runtime.h>
#include <cuda_bf16.h>
#include <cstdint>
#include <math.h>

// ---------------------------------------------------------------------------
// BertAdapter, 4-kernel split:
//   prep_t : transpose+bf16 weights (smem tiles)
//   ln     : x -> LN(x) bf16 (g_xn, L2-resident)   one pass, streaming
//   g1     : xn@Wd + gelu -> inter      PURE cp.async GEMM, 2 CTAs/SM
//   g2     : inter@Wu + bias + residual -> out     2 CTAs/SM
// mma.sync m16n8k16 bf16 (plain sm_103 target: no tcgen05).
// ---------------------------------------------------------------------------

#define TOKENS   32768
#define HIDDEN   1024
#define ADAPTER  256

__device__ __nv_bfloat16 g_wdT[HIDDEN * ADAPTER];   // wdT[n*1024 + k] = wd[k][n]
__device__ __nv_bfloat16 g_wuT[ADAPTER * HIDDEN];   // wuT[n*256  + k] = wu[k][n]
__device__ __nv_bfloat16 g_xn[TOKENS * HIDDEN];     // LN(x) bf16, 64MB
__device__ __nv_bfloat16 g_inter[TOKENS * ADAPTER]; // 16MB

// ---------------- helpers ----------------
static __device__ __forceinline__ uint32_t smem_u32(const void* p) {
    uint32_t a;
    asm("{ .reg .u64 t; cvta.to.shared.u64 t, %1; cvt.u32.u64 %0, t; }"
        : "=r"(a) : "l"(p));
    return a;
}
static __device__ __forceinline__ uint32_t sw128(uint32_t o) {
    return o ^ ((o >> 3) & 0x70);
}

#define LDMATRIX_X4(r0, r1, r2, r3, addr)                                      \
    asm volatile("ldmatrix.sync.aligned.m8n8.x4.shared.b16 {%0,%1,%2,%3}, [%4];" \
                 : "=r"(r0), "=r"(r1), "=r"(r2), "=r"(r3) : "r"(addr))

#define MMA_BF16(d, a, bb0, bb1)                                               \
    asm volatile(                                                              \
        "mma.sync.aligned.m16n8k16.row.col.f32.bf16.bf16.f32 "                 \
        "{%0,%1,%2,%3}, {%4,%5,%6,%7}, {%8,%9}, {%0,%1,%2,%3};"                \
        : "+f"((d)[0]), "+f"((d)[1]), "+f"((d)[2]), "+f"((d)[3])               \
        : "r"((a)[0]), "r"((a)[1]), "r"((a)[2]), "r"((a)[3]),                  \
          "r"(bb0), "r"(bb1))

#define CP_ASYNC16(dst, src)                                                   \
    asm volatile("cp.async.cg.shared.global [%0], [%1], 16;"                   \
                 :: "r"(dst), "l"(src))
#define CP_COMMIT() asm volatile("cp.async.commit_group;" ::: "memory")
#define CP_WAIT0()  asm volatile("cp.async.wait_group 0;" ::: "memory")

static __device__ __forceinline__ float gelu_new_f(float x) {
    float x3 = x * x * x;
    float t = tanhf(0.7978845608028654f * (x + 0.044715f * x3));
    return 0.5f * x * (1.0f + t);
}

struct Frag64 { float a[2][8][4]; };   // warp tile 32m x 64n

static __device__ __forceinline__ void tile_compute64(uint32_t ab, uint32_t bb,
                                                      int lid, int wm, int wn,
                                                      Frag64& f) {
#pragma unroll
    for (int kk = 0; kk < 4; kk++) {
        uint32_t a[2][4];
#pragma unroll
        for (int mt = 0; mt < 2; mt++) {
            uint32_t off = (uint32_t)(wm + mt * 16 + (lid & 15)) * 128u +
                           (uint32_t)(kk * 32 + ((lid >> 4) << 4));
            LDMATRIX_X4(a[mt][0], a[mt][1], a[mt][2], a[mt][3], ab + sw128(off));
        }
        uint32_t b[4][4];
#pragma unroll
        for (int g = 0; g < 4; g++) {
            uint32_t row = (uint32_t)(wn + g * 16 + (lid & 7) + ((lid >> 4) << 3));
            uint32_t off = row * 128u +
                           (uint32_t)(kk * 32 + (((lid >> 3) & 1) << 4));
            LDMATRIX_X4(b[g][0], b[g][1], b[g][2], b[g][3], bb + sw128(off));
        }
#pragma unroll
        for (int mt = 0; mt < 2; mt++)
#pragma unroll
            for (int nt = 0; nt < 8; nt++) {
                int g = nt >> 1;
                if ((nt & 1) == 0) MMA_BF16(f.a[mt][nt], a[mt], b[g][0], b[g][1]);
                else               MMA_BF16(f.a[mt][nt], a[mt], b[g][2], b[g][3]);
            }
    }
}

// ---------------- prep: smem-tile transpose + bf16 convert ----------------
__global__ void __launch_bounds__(256) prep_t(const float* __restrict__ wd,
                                              const float* __restrict__ wu) {
    __shared__ float t[32][33];
    int b = blockIdx.x;
    int r = threadIdx.x >> 5, c = threadIdx.x & 31;
    if (b < 256) {          // wd [1024k][256n] -> wdT [256n][1024k]
        int k0 = (b >> 3) * 32, n0 = (b & 7) * 32;
#pragma unroll
        for (int i = 0; i < 4; i++)
            t[r + i * 8][c] = wd[(size_t)(k0 + r + i * 8) * 256 + n0 + c];
        __syncthreads();
#pragma unroll
        for (int i = 0; i < 4; i++)
            g_wdT[(size_t)(n0 + r + i * 8) * 1024 + k0 + c] =
                __float2bfloat16(t[c][r + i * 8]);
    } else {                // wu [256k][1024n] -> wuT [1024n][256k]
        b -= 256;
        int k0 = (b & 7) * 32, n0 = (b >> 3) * 32;
#pragma unroll
        for (int i = 0; i < 4; i++)
            t[r + i * 8][c] = wu[(size_t)(k0 + r + i * 8) * 1024 + n0 + c];
        __syncthreads();
#pragma unroll
        for (int i = 0; i < 4; i++)
            g_wuT[(size_t)(n0 + r + i * 8) * 256 + k0 + c] =
                __float2bfloat16(t[c][r + i * 8]);
    }
}

// ---------------- ln: x -> LN(x) bf16, one pass, streaming ----------------
__global__ void __launch_bounds__(256) ln_kernel(const float* __restrict__ x,
                                                 const float* __restrict__ lnw,
                                                 const float* __restrict__ lnb) {
    int row = blockIdx.x * 8 + (threadIdx.x >> 5);
    int lid = threadIdx.x & 31;
    const float4* p = (const float4*)x + (size_t)row * 256;
    const float4* w4 = (const float4*)lnw;
    const float4* b4 = (const float4*)lnb;

    float4 v[8];
    float s = 0.f, ss = 0.f;
#pragma unroll
    for (int i = 0; i < 8; i++) {
        v[i] = p[lid + i * 32];
        s  += v[i].x + v[i].y + v[i].z + v[i].w;
        ss += v[i].x * v[i].x + v[i].y * v[i].y +
              v[i].z * v[i].z + v[i].w * v[i].w;
    }
#pragma unroll
    for (int o = 16; o; o >>= 1) {
        s  += __shfl_xor_sync(0xFFFFFFFFu, s, o);
        ss += __shfl_xor_sync(0xFFFFFFFFu, ss, o);
    }
    float mu = s * (1.0f / 1024.0f);
    float rs = rsqrtf(ss * (1.0f / 1024.0f) - mu * mu + 1e-5f);

    uint2* dst = (uint2*)(g_xn + (size_t)row * 1024);
#pragma unroll
    for (int i = 0; i < 8; i++) {
        int k4 = lid + i * 32;
        float4 w = w4[k4], b = b4[k4];
        __nv_bfloat162 p0 = __floats2bfloat162_rn((v[i].x - mu) * rs * w.x + b.x,
                                                  (v[i].y - mu) * rs * w.y + b.y);
        __nv_bfloat162 p1 = __floats2bfloat162_rn((v[i].z - mu) * rs * w.z + b.z,
                                                  (v[i].w - mu) * rs * w.w + b.w);
        uint2 val;
        val.x = *(uint32_t*)&p0;
        val.y = *(uint32_t*)&p1;
        __stcg(dst + k4, val);     // L2-resident, bypass L1
    }
}

// smem (1024-aligned): A0@0, A1@16384, B0@32768, B1@49152
#define G_A0 0u
#define G_A1 16384u
#define G_B0 32768u
#define G_B1 49152u
#define G_SMEM (65536 + 1024)

// ---------------- g1: xn@Wd + gelu -> inter (pure GEMM) -------------------
__global__ void __launch_bounds__(256, 2)
g1_kernel(const float* __restrict__ bdown) {
    extern __shared__ char smem_raw[];
    const int tid = threadIdx.x, wid = tid >> 5, lid = tid & 31;
    const int m0 = blockIdx.x * 128;
    const int n0 = blockIdx.y * 128;

    uint32_t sb0 = smem_u32(smem_raw);
    uint32_t pad = (1024u - (sb0 & 1023u)) & 1023u;
    uint32_t sb = sb0 + pad;

    const uint4* xn4  = (const uint4*)g_xn;     // 128 uint4 per 1024-bf16 row
    const uint4* wdT4 = (const uint4*)g_wdT;    // 128 uint4 per row

    auto loadAB = [&](int kt, uint32_t abuf, uint32_t bbuf) {   // 16KB each
#pragma unroll
        for (int i = 0; i < 4; i++) {
            int idx = tid + i * 256;
            int r = idx >> 3, u = idx & 7;
            uint32_t so = sw128((uint32_t)r * 128u + (uint32_t)u * 16u);
            CP_ASYNC16(abuf + so, xn4  + (size_t)(m0 + r) * 128 + kt * 8 + u);
            CP_ASYNC16(bbuf + so, wdT4 + (size_t)(n0 + r) * 128 + kt * 8 + u);
        }
        CP_COMMIT();
    };

    Frag64 f1;
#pragma unroll
    for (int mt = 0; mt < 2; mt++)
#pragma unroll
        for (int nt = 0; nt < 8; nt++)
#pragma unroll
            for (int j = 0; j < 4; j++) f1.a[mt][nt][j] = 0.f;

    const int wm = (wid & 3) * 32, wn = (wid >> 2) * 64;

    loadAB(0, sb + G_A0, sb + G_B0);
    CP_WAIT0();
    __syncthreads();

#pragma unroll 1
    for (int kt = 0; kt < 16; kt++) {
        int buf = kt & 1;
        if (kt + 1 < 16)
            loadAB(kt + 1, sb + (buf ? G_A0 : G_A1), sb + (buf ? G_B0 : G_B1));
        tile_compute64(sb + (buf ? G_A1 : G_A0),
                       sb + (buf ? G_B1 : G_B0), lid, wm, wn, f1);
        CP_WAIT0();
        __syncthreads();
    }

    // gelu + bias -> inter (bf16)
    uint32_t* dst = (uint32_t*)g_inter;
#pragma unroll
    for (int mt = 0; mt < 2; mt++)
#pragma unroll
        for (int nt = 0; nt < 8; nt++) {
            int col = n0 + wn + nt * 8 + (lid & 3) * 2;
            int row = m0 + wm + mt * 16 + (lid >> 2);
            float b0 = bdown[col], b1 = bdown[col + 1];
            float* c = f1.a[mt][nt];
            __nv_bfloat162 p0 = __floats2bfloat162_rn(gelu_new_f(c[0] + b0),
                                                      gelu_new_f(c[1] + b1));
            __nv_bfloat162 p1 = __floats2bfloat162_rn(gelu_new_f(c[2] + b0),
                                                      gelu_new_f(c[3] + b1));
            dst[(size_t)row * 128 + (col >> 1)]       = *(uint32_t*)&p0;
            dst[(size_t)(row + 8) * 128 + (col >> 1)] = *(uint32_t*)&p1;
        }
}

// ---------------- g2: inter@Wu + bias + residual -> out -------------------
__global__ void __launch_bounds__(256, 2)
g2_kernel(const float* __restrict__ x, const float* __restrict__ bup,
          float* __restrict__ out) {
    extern __shared__ char smem_raw[];
    const int tid = threadIdx.x, wid = tid >> 5, lid = tid & 31;
    const int m0 = blockIdx.x * 128;
    const int n0 = blockIdx.y * 128;

    uint32_t sb0 = smem_u32(smem_raw);
    uint32_t pad = (1024u - (sb0 & 1023u)) & 1023u;
    uint32_t sb = sb0 + pad;

    const uint4* a4  = (const uint4*)g_inter;   // 32 uint4 per 256-bf16 row
    const uint4* wt4 = (const uint4*)g_wuT;     // 32 uint4 per row

    auto loadAB = [&](int kt, uint32_t abuf, uint32_t bbuf) {   // 16KB each
#pragma unroll
        for (int i = 0; i < 4; i++) {
            int idx = tid + i * 256;
            int r = idx >> 3, u = idx & 7;
            uint32_t so = sw128((uint32_t)r * 128u + (uint32_t)u * 16u);
            CP_ASYNC16(abuf + so, a4  + (size_t)(m0 + r) * 32 + kt * 8 + u);
            CP_ASYNC16(bbuf + so, wt4 + (size_t)(n0 + r) * 32 + kt * 8 + u);
        }
        CP_COMMIT();
    };

    Frag64 f2;
#pragma unroll
    for (int mt = 0; mt < 2; mt++)
#pragma unroll
        for (int nt = 0; nt < 8; nt++)
#pragma unroll
            for (int j = 0; j < 4; j++) f2.a[mt][nt][j] = 0.f;

    const int wm = (wid & 3) * 32, wn = (wid >> 2) * 64;

    loadAB(0, sb + G_A0, sb + G_B0);
    CP_WAIT0();
    __syncthreads();

#pragma unroll 1
    for (int kt = 0; kt < 4; kt++) {
        int buf = kt & 1;
        if (kt + 1 < 4)
            loadAB(kt + 1, sb + (buf ? G_A0 : G_A1), sb + (buf ? G_B0 : G_B1));
        tile_compute64(sb + (buf ? G_A1 : G_A0),
                       sb + (buf ? G_B1 : G_B0), lid, wm, wn, f2);
        CP_WAIT0();
        __syncthreads();
    }

    const float2* x2  = (const float2*)x;
    const float2* bu2 = (const float2*)bup;
    float2* o2 = (float2*)out;
#pragma unroll
    for (int mt = 0; mt < 2; mt++)
#pragma unroll
        for (int nt = 0; nt < 8; nt++) {
            int col = n0 + wn + nt * 8 + (lid & 3) * 2;
            int row = m0 + wm + mt * 16 + (lid >> 2);
            float2 bv = bu2[col >> 1];
            float* c = f2.a[mt][nt];
            float2 r0 = x2[(size_t)row * 512 + (col >> 1)];
            float2 r1 = x2[(size_t)(row + 8) * 512 + (col >> 1)];
            float2 o0, o1;
            o0.x = c[0] + bv.x + r0.x;  o0.y = c[1] + bv.y + r0.y;
            o1.x = c[2] + bv.x + r1.x;  o1.y = c[3] + bv.y + r1.y;
            o2[(size_t)row * 512 + (col >> 1)]       = o0;
            o2[(size_t)(row + 8) * 512 + (col >> 1)] = o1;
        }
}

// ---------------- host launcher ----------------
extern "C" void kernel_launch(void* const* d_in, const int* in_sizes, int n_in,
                              void* d_out, int out_size) {
    const float* x   = (const float*)d_in[0];
    const float* lnw = (const float*)d_in[1];
    const float* lnb = (const float*)d_in[2];
    const float* wd  = (const float*)d_in[3];
    const float* bd  = (const float*)d_in[4];
    const float* wu  = (const float*)d_in[5];
    const float* bu  = (const float*)d_in[6];
    float* out = (float*)d_out;

    cudaFuncSetAttribute(g1_kernel, cudaFuncAttributeMaxDynamicSharedMemorySize,
                         G_SMEM);
    cudaFuncSetAttribute(g2_kernel, cudaFuncAttributeMaxDynamicSharedMemorySize,
                         G_SMEM);

    prep_t<<<512, 256>>>(wd, wu);
    ln_kernel<<<4096, 256>>>(x, lnw, lnb);
    g1_kernel<<<dim3(256, 2), 256, G_SMEM>>>(bd);
    g2_kernel<<<dim3(256, 8), 256, G_SMEM>>>(x, bu, out);
    (void)in_sizes; (void)n_in; (void)out_size;
}